// round 16
// baseline (speedup 1.0000x reference)
#include <cuda_runtime.h>
#include <cuda_bf16.h>
#include <cuda_fp16.h>
#include <math.h>

#define N_NODES 50000
#define N_FEAT 512
#define HIDDEN 128
#define N_CLASSES 40
#define E_MAX 1600000
#define SCAN_BLOCKS ((N_NODES + 255) / 256)   // 196

// ---------------- scratch (device globals: no allocation allowed) ----------
__device__ float    g_dinv[N_NODES];
__device__ int      g_cnt[N_NODES];
__device__ int      g_off[N_NODES + 1];
__device__ int      g_pos[N_NODES];
__device__ int      g_blocksum[SCAN_BLOCKS];
__device__ int      g_blockoff[SCAN_BLOCKS];
__device__ int      g_csr_src[E_MAX];
__device__ __half   g_hh[N_NODES * HIDDEN];      // fp16 h = x @ W1 (UNscaled)
__device__ __half   g_h116[N_NODES * HIDDEN];    // fp16 relu(conv1)
__device__ __half   g_lp16[N_NODES * N_CLASSES]; // fp16 lp_pre = dinv * (h1 @ W2)
__device__ unsigned g_W1hi[(N_FEAT / 2) * HIDDEN];   // pre-split W1, bf16x2 [k2][n]
__device__ unsigned g_W1lo[(N_FEAT / 2) * HIDDEN];
__device__ int      g_is64;                      // edge_index dtype flag

// ---------------- bf16 split helper -----------------------------------------
__device__ __forceinline__ void bf16_split2(float x, float y,
                                            unsigned& hi, unsigned& lo) {
    __nv_bfloat16 hx = __float2bfloat16(x);
    __nv_bfloat16 hy = __float2bfloat16(y);
    float lxf = x - __bfloat162float(hx);
    float lyf = y - __bfloat162float(hy);
    __nv_bfloat16 lx = __float2bfloat16(lxf);
    __nv_bfloat16 ly = __float2bfloat16(lyf);
    hi = ((unsigned)__bfloat16_as_ushort(hy) << 16) | (unsigned)__bfloat16_as_ushort(hx);
    lo = ((unsigned)__bfloat16_as_ushort(ly) << 16) | (unsigned)__bfloat16_as_ushort(lx);
}

// ---------------- edge index access (int32 / int64 hedge) ------------------
__device__ __forceinline__ int edge_at(const void* ei, int idx, int is64) {
    if (is64) return (int)((const long long*)ei)[idx];
    return ((const int*)ei)[idx];
}

// zero histogram + detect edge dtype + pre-split W1 to bf16 hi/lo
__global__ void k_zero_cnt(const int* __restrict__ e32,
                           const float* __restrict__ W1) {
    int i = blockIdx.x * blockDim.x + threadIdx.x;
    if (i < N_NODES) g_cnt[i] = 0;
    if (i < (N_FEAT / 2) * HIDDEN) {
        int k2 = i >> 7, n = i & 127;
        float x0 = W1[(size_t)(k2 * 2 + 0) * HIDDEN + n];
        float x1 = W1[(size_t)(k2 * 2 + 1) * HIDDEN + n];
        unsigned h, l;
        bf16_split2(x0, x1, h, l);
        g_W1hi[i] = h;
        g_W1lo[i] = l;
    }
    if (i == 0) {
        bool is64 = true;
        for (int k = 1; k < 64; k += 2) {
            if (e32[k] != 0) { is64 = false; break; }
        }
        g_is64 = is64 ? 1 : 0;
    }
}

__global__ void k_hist(const void* __restrict__ ei, int E) {
    int i = blockIdx.x * blockDim.x + threadIdx.x;
    if (i >= E) return;
    int d = edge_at(ei, E + i, g_is64);
    atomicAdd(&g_cnt[d], 1);
}

// ---------------- hierarchical scan (3 phases, coalesced) -------------------
__global__ __launch_bounds__(256) void k_scan1() {
    __shared__ int sh[256];
    int tid = threadIdx.x;
    int i = blockIdx.x * 256 + tid;
    int c = (i < N_NODES) ? g_cnt[i] : 0;
    sh[tid] = c;
    __syncthreads();
    for (int off = 1; off < 256; off <<= 1) {
        int v = (tid >= off) ? sh[tid - off] : 0;
        __syncthreads();
        sh[tid] += v;
        __syncthreads();
    }
    int incl = sh[tid];
    if (i < N_NODES) g_off[i] = incl - c;
    if (tid == 255) g_blocksum[blockIdx.x] = incl;
}

__global__ __launch_bounds__(256) void k_scan2() {
    __shared__ int sh[256];
    int tid = threadIdx.x;
    int c = (tid < SCAN_BLOCKS) ? g_blocksum[tid] : 0;
    sh[tid] = c;
    __syncthreads();
    for (int off = 1; off < 256; off <<= 1) {
        int v = (tid >= off) ? sh[tid - off] : 0;
        __syncthreads();
        sh[tid] += v;
        __syncthreads();
    }
    if (tid < SCAN_BLOCKS) g_blockoff[tid] = sh[tid] - c;
    if (tid == 255) g_off[N_NODES] = sh[255];
}

__global__ __launch_bounds__(256) void k_scan3() {
    int i = blockIdx.x * 256 + threadIdx.x;
    if (i >= N_NODES) return;
    int off = g_off[i] + g_blockoff[blockIdx.x];
    g_off[i] = off;
    g_pos[i] = off;
    g_dinv[i] = rsqrtf((float)(g_cnt[i] + 1));   // + self loop
}

__global__ void k_scatter(const void* __restrict__ ei, int E) {
    int i = blockIdx.x * blockDim.x + threadIdx.x;
    if (i >= E) return;
    int is64 = g_is64;
    int s = edge_at(ei, i, is64);
    int d = edge_at(ei, E + i, is64);
    int p = atomicAdd(&g_pos[d], 1);
    g_csr_src[p] = s;
}

// ---------------- GEMM1 (tensor cores, bf16x3): g_hh = fp16(x @ W1) ---------
#define MMA_BF16(c, a, b)                                                     \
    asm volatile(                                                             \
        "mma.sync.aligned.m16n8k16.row.col.f32.bf16.bf16.f32 "                \
        "{%0,%1,%2,%3},{%4,%5,%6,%7},{%8,%9},{%0,%1,%2,%3};"                  \
        : "+f"((c)[0]), "+f"((c)[1]), "+f"((c)[2]), "+f"((c)[3])              \
        : "r"((a)[0]), "r"((a)[1]), "r"((a)[2]), "r"((a)[3]),                 \
          "r"((b)[0]), "r"((b)[1]))

#define SMS 136   // smem row stride in 4B words

__global__ __launch_bounds__(256) void k_sgemm1(const float* __restrict__ A) {
    const int K = N_FEAT, N = HIDDEN, M = N_NODES;
    const int NT = K / 16;   // 32 K-tiles

    __shared__ __align__(16) unsigned As_hi[2][8][SMS];
    __shared__ __align__(16) unsigned As_lo[2][8][SMS];
    __shared__ __align__(16) unsigned Bs_hi[2][8][SMS];
    __shared__ __align__(16) unsigned Bs_lo[2][8][SMS];

    int tid  = threadIdx.x;
    int lane = tid & 31;
    int wid  = tid >> 5;
    int gid  = lane >> 2;
    int tg   = lane & 3;
    int wm   = (wid >> 2) * 64;
    int wn   = (wid & 3) * 32;
    int blockM = blockIdx.x * 128;

    int a_row = tid >> 1;
    int a_q   = tid & 1;
    int a_rowg = blockM + a_row;
    if (a_rowg > M - 1) a_rowg = M - 1;
    const float* Arow = A + (size_t)a_rowg * K + a_q * 8;

    int b_k2 = tid >> 5;
    int b_n0 = (tid & 31) * 4;

    float c[4][4][4];
#pragma unroll
    for (int mi = 0; mi < 4; mi++)
#pragma unroll
        for (int ni = 0; ni < 4; ni++)
#pragma unroll
            for (int r = 0; r < 4; r++) c[mi][ni][r] = 0.0f;

    float4 fa0, fa1;
    uint4  pbh, pbl;
    fa0 = *(const float4*)(Arow + 0);
    fa1 = *(const float4*)(Arow + 4);
    pbh = *(const uint4*)&g_W1hi[(size_t)b_k2 * HIDDEN + b_n0];
    pbl = *(const uint4*)&g_W1lo[(size_t)b_k2 * HIDDEN + b_n0];

    for (int t = 0; t < NT; t++) {
        int buf = t & 1;
        {
            unsigned h, l;
            int k2b = a_q * 4;
            bf16_split2(fa0.x, fa0.y, h, l);
            As_hi[buf][k2b + 0][a_row] = h; As_lo[buf][k2b + 0][a_row] = l;
            bf16_split2(fa0.z, fa0.w, h, l);
            As_hi[buf][k2b + 1][a_row] = h; As_lo[buf][k2b + 1][a_row] = l;
            bf16_split2(fa1.x, fa1.y, h, l);
            As_hi[buf][k2b + 2][a_row] = h; As_lo[buf][k2b + 2][a_row] = l;
            bf16_split2(fa1.z, fa1.w, h, l);
            As_hi[buf][k2b + 3][a_row] = h; As_lo[buf][k2b + 3][a_row] = l;
        }
        *(uint4*)&Bs_hi[buf][b_k2][b_n0] = pbh;
        *(uint4*)&Bs_lo[buf][b_k2][b_n0] = pbl;
        __syncthreads();

        if (t + 1 < NT) {
            int kt = (t + 1) * 16;
            fa0 = *(const float4*)(Arow + kt + 0);
            fa1 = *(const float4*)(Arow + kt + 4);
            size_t bidx = (size_t)((t + 1) * 8 + b_k2) * HIDDEN + b_n0;
            pbh = *(const uint4*)&g_W1hi[bidx];
            pbl = *(const uint4*)&g_W1lo[bidx];
        }

        unsigned bh[4][2], bl[4][2];
#pragma unroll
        for (int ni = 0; ni < 4; ni++) {
            int col = wn + ni * 8 + gid;
            bh[ni][0] = Bs_hi[buf][tg][col];
            bh[ni][1] = Bs_hi[buf][tg + 4][col];
            bl[ni][0] = Bs_lo[buf][tg][col];
            bl[ni][1] = Bs_lo[buf][tg + 4][col];
        }
#pragma unroll
        for (int mi = 0; mi < 4; mi++) {
            int r = wm + mi * 16 + gid;
            unsigned ah[4], al[4];
            ah[0] = As_hi[buf][tg][r];     ah[1] = As_hi[buf][tg][r + 8];
            ah[2] = As_hi[buf][tg + 4][r]; ah[3] = As_hi[buf][tg + 4][r + 8];
            al[0] = As_lo[buf][tg][r];     al[1] = As_lo[buf][tg][r + 8];
            al[2] = As_lo[buf][tg + 4][r]; al[3] = As_lo[buf][tg + 4][r + 8];
#pragma unroll
            for (int ni = 0; ni < 4; ni++) MMA_BF16(c[mi][ni], ah, bh[ni]);
#pragma unroll
            for (int ni = 0; ni < 4; ni++) MMA_BF16(c[mi][ni], ah, bl[ni]);
#pragma unroll
            for (int ni = 0; ni < 4; ni++) MMA_BF16(c[mi][ni], al, bh[ni]);
        }
    }

#pragma unroll
    for (int mi = 0; mi < 4; mi++) {
        int r0 = blockM + wm + mi * 16 + gid;
        int r1 = r0 + 8;
#pragma unroll
        for (int ni = 0; ni < 4; ni++) {
            int col = wn + ni * 8 + tg * 2;
            if (r0 < M)
                *(__half2*)&g_hh[(size_t)r0 * N + col] =
                    __floats2half2_rn(c[mi][ni][0], c[mi][ni][1]);
            if (r1 < M)
                *(__half2*)&g_hh[(size_t)r1 * N + col] =
                    __floats2half2_rn(c[mi][ni][2], c[mi][ni][3]);
        }
    }
}

// ---------------- layer-1 aggregation: TWO nodes per warp, 4-edge batches ---
// Two independent gather chains per warp overlap each other's L2 latency.
__global__ __launch_bounds__(256) void k_agg1(const float* __restrict__ b1) {
    int w = (blockIdx.x * blockDim.x + threadIdx.x) >> 5;
    int n0 = w * 2;
    if (n0 >= N_NODES) return;
    int n1 = n0 + 1;
    bool has1 = (n1 < N_NODES);
    int lane = threadIdx.x & 31;

    const uint2* hp = (const uint2*)g_hh;
    float di0 = g_dinv[n0];
    float di1 = has1 ? g_dinv[n1] : 0.0f;
    int e0 = g_off[n0], end0 = g_off[n0 + 1];
    int e1 = has1 ? g_off[n1] : 0, end1 = has1 ? g_off[n1 + 1] : 0;

    float ax0, ay0, az0, aw0, ax1 = 0, ay1 = 0, az1 = 0, aw1 = 0;
    {
        uint2 raw = __ldg(&hp[(size_t)n0 * 32 + lane]);   // self loop n0
        float2 f0 = __half22float2(*(__half2*)&raw.x);
        float2 f1 = __half22float2(*(__half2*)&raw.y);
        ax0 = di0 * f0.x; ay0 = di0 * f0.y; az0 = di0 * f1.x; aw0 = di0 * f1.y;
    }
    if (has1) {
        uint2 raw = __ldg(&hp[(size_t)n1 * 32 + lane]);   // self loop n1
        float2 f0 = __half22float2(*(__half2*)&raw.x);
        float2 f1 = __half22float2(*(__half2*)&raw.y);
        ax1 = di1 * f0.x; ay1 = di1 * f0.y; az1 = di1 * f1.x; aw1 = di1 * f1.y;
    }

    // lockstep: both nodes have >= 4 edges remaining (two independent chains)
    while (e0 + 4 <= end0 && e1 + 4 <= end1) {
        int   s0[4], s1[4];
        float w0[4], w1[4];
        uint2 r0[4], r1[4];
#pragma unroll
        for (int j = 0; j < 4; j++) s0[j] = __ldg(&g_csr_src[e0 + j]);
#pragma unroll
        for (int j = 0; j < 4; j++) s1[j] = __ldg(&g_csr_src[e1 + j]);
#pragma unroll
        for (int j = 0; j < 4; j++) w0[j] = __ldg(&g_dinv[s0[j]]);
#pragma unroll
        for (int j = 0; j < 4; j++) w1[j] = __ldg(&g_dinv[s1[j]]);
#pragma unroll
        for (int j = 0; j < 4; j++) r0[j] = __ldg(&hp[(size_t)s0[j] * 32 + lane]);
#pragma unroll
        for (int j = 0; j < 4; j++) r1[j] = __ldg(&hp[(size_t)s1[j] * 32 + lane]);
#pragma unroll
        for (int j = 0; j < 4; j++) {
            float2 a = __half22float2(*(__half2*)&r0[j].x);
            float2 b = __half22float2(*(__half2*)&r0[j].y);
            ax0 += w0[j] * a.x; ay0 += w0[j] * a.y;
            az0 += w0[j] * b.x; aw0 += w0[j] * b.y;
        }
#pragma unroll
        for (int j = 0; j < 4; j++) {
            float2 a = __half22float2(*(__half2*)&r1[j].x);
            float2 b = __half22float2(*(__half2*)&r1[j].y);
            ax1 += w1[j] * a.x; ay1 += w1[j] * a.y;
            az1 += w1[j] * b.x; aw1 += w1[j] * b.y;
        }
        e0 += 4; e1 += 4;
    }
    // drain node 0
    for (; e0 + 4 <= end0; e0 += 4) {
        int   s[4]; float wt[4]; uint2 r[4];
#pragma unroll
        for (int j = 0; j < 4; j++) s[j] = __ldg(&g_csr_src[e0 + j]);
#pragma unroll
        for (int j = 0; j < 4; j++) wt[j] = __ldg(&g_dinv[s[j]]);
#pragma unroll
        for (int j = 0; j < 4; j++) r[j] = __ldg(&hp[(size_t)s[j] * 32 + lane]);
#pragma unroll
        for (int j = 0; j < 4; j++) {
            float2 a = __half22float2(*(__half2*)&r[j].x);
            float2 b = __half22float2(*(__half2*)&r[j].y);
            ax0 += wt[j] * a.x; ay0 += wt[j] * a.y;
            az0 += wt[j] * b.x; aw0 += wt[j] * b.y;
        }
    }
    for (; e0 < end0; e0++) {
        int s = __ldg(&g_csr_src[e0]);
        float wt = __ldg(&g_dinv[s]);
        uint2 r = __ldg(&hp[(size_t)s * 32 + lane]);
        float2 a = __half22float2(*(__half2*)&r.x);
        float2 b = __half22float2(*(__half2*)&r.y);
        ax0 += wt * a.x; ay0 += wt * a.y; az0 += wt * b.x; aw0 += wt * b.y;
    }
    // drain node 1
    for (; e1 + 4 <= end1; e1 += 4) {
        int   s[4]; float wt[4]; uint2 r[4];
#pragma unroll
        for (int j = 0; j < 4; j++) s[j] = __ldg(&g_csr_src[e1 + j]);
#pragma unroll
        for (int j = 0; j < 4; j++) wt[j] = __ldg(&g_dinv[s[j]]);
#pragma unroll
        for (int j = 0; j < 4; j++) r[j] = __ldg(&hp[(size_t)s[j] * 32 + lane]);
#pragma unroll
        for (int j = 0; j < 4; j++) {
            float2 a = __half22float2(*(__half2*)&r[j].x);
            float2 b = __half22float2(*(__half2*)&r[j].y);
            ax1 += wt[j] * a.x; ay1 += wt[j] * a.y;
            az1 += wt[j] * b.x; aw1 += wt[j] * b.y;
        }
    }
    for (; e1 < end1; e1++) {
        int s = __ldg(&g_csr_src[e1]);
        float wt = __ldg(&g_dinv[s]);
        uint2 r = __ldg(&hp[(size_t)s * 32 + lane]);
        float2 a = __half22float2(*(__half2*)&r.x);
        float2 b = __half22float2(*(__half2*)&r.y);
        ax1 += wt * a.x; ay1 += wt * a.y; az1 += wt * b.x; aw1 += wt * b.y;
    }

    float4 bb = *(const float4*)&b1[lane * 4];
    {
        uint2 st;
        *(__half2*)&st.x = __floats2half2_rn(fmaxf(di0 * ax0 + bb.x, 0.0f),
                                             fmaxf(di0 * ay0 + bb.y, 0.0f));
        *(__half2*)&st.y = __floats2half2_rn(fmaxf(di0 * az0 + bb.z, 0.0f),
                                             fmaxf(di0 * aw0 + bb.w, 0.0f));
        *(uint2*)&g_h116[(size_t)n0 * HIDDEN + lane * 4] = st;
    }
    if (has1) {
        uint2 st;
        *(__half2*)&st.x = __floats2half2_rn(fmaxf(di1 * ax1 + bb.x, 0.0f),
                                             fmaxf(di1 * ay1 + bb.y, 0.0f));
        *(__half2*)&st.y = __floats2half2_rn(fmaxf(di1 * az1 + bb.z, 0.0f),
                                             fmaxf(di1 * aw1 + bb.w, 0.0f));
        *(uint2*)&g_h116[(size_t)n1 * HIDDEN + lane * 4] = st;
    }
}

// ---------------- GEMM2: g_lp16 = fp16(dinv * (h1 @ W2)), fp16 h1 input -----
__global__ __launch_bounds__(256) void k_gemm2(const float* __restrict__ W2) {
    __shared__ float sW[HIDDEN * N_CLASSES];
    __shared__ float sH[32 * HIDDEN];
    int tid = threadIdx.x;
    int row0 = blockIdx.x * 32;

    for (int i = tid; i < HIDDEN * N_CLASSES; i += 256) sW[i] = W2[i];
    for (int i = tid; i < 32 * HIDDEN / 4; i += 256) {
        int r = i >> 5;
        int c4 = i & 31;
        int grow = row0 + r;
        float4 v = make_float4(0.f, 0.f, 0.f, 0.f);
        if (grow < N_NODES) {
            uint2 raw = *(const uint2*)&g_h116[(size_t)grow * HIDDEN + c4 * 4];
            float2 f0 = __half22float2(*(__half2*)&raw.x);
            float2 f1 = __half22float2(*(__half2*)&raw.y);
            v = make_float4(f0.x, f0.y, f1.x, f1.y);
        }
        *(float4*)&sH[r * HIDDEN + c4 * 4] = v;
    }
    __syncthreads();

#pragma unroll
    for (int p = 0; p < 5; p++) {
        int o = tid + p * 256;
        int r = o / N_CLASSES;
        int c = o - r * N_CLASSES;
        float acc = 0.0f;
#pragma unroll 8
        for (int k = 0; k < HIDDEN; k++) acc += sH[r * HIDDEN + k] * sW[k * N_CLASSES + c];
        int grow = row0 + r;
        if (grow < N_NODES)
            g_lp16[(size_t)grow * N_CLASSES + c] = __float2half(g_dinv[grow] * acc);
    }
}

// ---------------- layer-2 agg: TWO nodes per warp + bias + log_softmax ------
__global__ __launch_bounds__(256) void k_agg2(const float* __restrict__ b2,
                                              float* __restrict__ out,
                                              int write_logits) {
    int w = (blockIdx.x * blockDim.x + threadIdx.x) >> 5;
    int n0 = w * 2;
    if (n0 >= N_NODES) return;
    int n1 = n0 + 1;
    bool has1 = (n1 < N_NODES);
    int lane = threadIdx.x & 31;
    bool act = (lane < 20);

    const __half2* lp = (const __half2*)g_lp16;   // 20 half2 per row
    float di0 = g_dinv[n0];
    float di1 = has1 ? g_dinv[n1] : 0.0f;
    int e0 = g_off[n0], end0 = g_off[n0 + 1];
    int e1 = has1 ? g_off[n1] : 0, end1 = has1 ? g_off[n1 + 1] : 0;

    float a00 = 0, a01 = 0, a10 = 0, a11 = 0;
    if (act) {
        float2 f = __half22float2(__ldg(&lp[(size_t)n0 * 20 + lane]));
        a00 = f.x; a01 = f.y;
        if (has1) {
            float2 g = __half22float2(__ldg(&lp[(size_t)n1 * 20 + lane]));
            a10 = g.x; a11 = g.y;
        }
    }

    while (e0 + 4 <= end0 && e1 + 4 <= end1) {
        int s0[4], s1[4];
#pragma unroll
        for (int j = 0; j < 4; j++) s0[j] = __ldg(&g_csr_src[e0 + j]);
#pragma unroll
        for (int j = 0; j < 4; j++) s1[j] = __ldg(&g_csr_src[e1 + j]);
        if (act) {
            __half2 r0[4], r1[4];
#pragma unroll
            for (int j = 0; j < 4; j++) r0[j] = __ldg(&lp[(size_t)s0[j] * 20 + lane]);
#pragma unroll
            for (int j = 0; j < 4; j++) r1[j] = __ldg(&lp[(size_t)s1[j] * 20 + lane]);
#pragma unroll
            for (int j = 0; j < 4; j++) {
                float2 f = __half22float2(r0[j]);
                a00 += f.x; a01 += f.y;
            }
#pragma unroll
            for (int j = 0; j < 4; j++) {
                float2 f = __half22float2(r1[j]);
                a10 += f.x; a11 += f.y;
            }
        }
        e0 += 4; e1 += 4;
    }
    for (; e0 < end0; e0++) {
        int s = __ldg(&g_csr_src[e0]);
        if (act) {
            float2 f = __half22float2(__ldg(&lp[(size_t)s * 20 + lane]));
            a00 += f.x; a01 += f.y;
        }
    }
    for (; e1 < end1; e1++) {
        int s = __ldg(&g_csr_src[e1]);
        if (act) {
            float2 f = __half22float2(__ldg(&lp[(size_t)s * 20 + lane]));
            a10 += f.x; a11 += f.y;
        }
    }

    float bb0 = act ? b2[lane * 2 + 0] : 0.0f;
    float bb1 = act ? b2[lane * 2 + 1] : 0.0f;

    // node 0 softmax
    {
        float v0 = act ? di0 * a00 + bb0 : -INFINITY;
        float v1 = act ? di0 * a01 + bb1 : -INFINITY;
        float m = fmaxf(v0, v1);
#pragma unroll
        for (int off = 16; off > 0; off >>= 1)
            m = fmaxf(m, __shfl_xor_sync(0xFFFFFFFFu, m, off));
        float sum = act ? (__expf(v0 - m) + __expf(v1 - m)) : 0.0f;
#pragma unroll
        for (int off = 16; off > 0; off >>= 1)
            sum += __shfl_xor_sync(0xFFFFFFFFu, sum, off);
        float lse = m + logf(sum);
        if (act) {
            *(float2*)&out[(size_t)n0 * N_CLASSES + lane * 2] =
                make_float2(v0 - lse, v1 - lse);
            if (write_logits)
                *(float2*)&out[(size_t)N_NODES * N_CLASSES + (size_t)n0 * N_CLASSES + lane * 2] =
                    make_float2(v0, v1);
        }
    }
    // node 1 softmax
    if (has1) {
        float v0 = act ? di1 * a10 + bb0 : -INFINITY;
        float v1 = act ? di1 * a11 + bb1 : -INFINITY;
        float m = fmaxf(v0, v1);
#pragma unroll
        for (int off = 16; off > 0; off >>= 1)
            m = fmaxf(m, __shfl_xor_sync(0xFFFFFFFFu, m, off));
        float sum = act ? (__expf(v0 - m) + __expf(v1 - m)) : 0.0f;
#pragma unroll
        for (int off = 16; off > 0; off >>= 1)
            sum += __shfl_xor_sync(0xFFFFFFFFu, sum, off);
        float lse = m + logf(sum);
        if (act) {
            *(float2*)&out[(size_t)n1 * N_CLASSES + lane * 2] =
                make_float2(v0 - lse, v1 - lse);
            if (write_logits)
                *(float2*)&out[(size_t)N_NODES * N_CLASSES + (size_t)n1 * N_CLASSES + lane * 2] =
                    make_float2(v0, v1);
        }
    }
}

// ---------------- launch -----------------------------------------------------
extern "C" void kernel_launch(void* const* d_in, const int* in_sizes, int n_in,
                              void* d_out, int out_size) {
    const float* x  = (const float*)d_in[0];
    const void*  ei = d_in[1];
    const float* W1 = (const float*)d_in[2];
    const float* b1 = (const float*)d_in[3];
    const float* W2 = (const float*)d_in[4];
    const float* b2 = (const float*)d_in[5];
    float* out = (float*)d_out;

    int E = in_sizes[1] / 2;
    if (E > E_MAX) E = E_MAX;
    int write_logits = (out_size >= 2 * N_NODES * N_CLASSES) ? 1 : 0;

    // side stream + fork/join events, created once on the first (un-captured) call.
    static cudaStream_t s2 = nullptr;
    static cudaEvent_t  evFork = nullptr, evJoin = nullptr;
    if (s2 == nullptr) {
        cudaStreamCreateWithFlags(&s2, cudaStreamNonBlocking);
        cudaEventCreateWithFlags(&evFork, cudaEventDisableTiming);
        cudaEventCreateWithFlags(&evJoin, cudaEventDisableTiming);
    }

    const int NPAIRS = (N_NODES + 1) / 2;   // 25000 warps for 2-node kernels

    // stream 0: W1 split + zero cnt
    k_zero_cnt<<<(N_NODES + 255) / 256, 256>>>((const int*)ei, W1);

    // fork: GEMM1 on s2; CSR build on stream 0 (hidden behind GEMM1)
    cudaEventRecord(evFork, 0);
    cudaStreamWaitEvent(s2, evFork, 0);
    k_sgemm1<<<(N_NODES + 127) / 128, 256, 0, s2>>>(x);
    cudaEventRecord(evJoin, s2);

    k_hist<<<(E + 255) / 256, 256>>>(ei, E);
    k_scan1<<<SCAN_BLOCKS, 256>>>();
    k_scan2<<<1, 256>>>();
    k_scan3<<<SCAN_BLOCKS, 256>>>();
    k_scatter<<<(E + 255) / 256, 256>>>(ei, E);

    // join: agg1 needs GEMM1 output + CSR + dinv; serial tail
    cudaStreamWaitEvent(0, evJoin, 0);
    k_agg1<<<(NPAIRS * 32 + 255) / 256, 256>>>(b1);
    k_gemm2<<<(N_NODES + 31) / 32, 256>>>(W2);
    k_agg2<<<(NPAIRS * 32 + 255) / 256, 256>>>(b2, out, write_logits);
}

// round 17
// speedup vs baseline: 1.0507x; 1.0507x over previous
#include <cuda_runtime.h>
#include <cuda_bf16.h>
#include <cuda_fp16.h>
#include <math.h>

#define N_NODES 50000
#define N_FEAT 512
#define HIDDEN 128
#define N_CLASSES 40
#define E_MAX 1600000
#define SCAN_BLOCKS ((N_NODES + 255) / 256)   // 196

// ---------------- scratch (device globals: no allocation allowed) ----------
__device__ float    g_dinv[N_NODES];
__device__ int      g_cnt[N_NODES];
__device__ int      g_off[N_NODES + 1];
__device__ int      g_pos[N_NODES];
__device__ int      g_blocksum[SCAN_BLOCKS];
__device__ int      g_blockoff[SCAN_BLOCKS];
__device__ int      g_csr_src[E_MAX];
__device__ __half   g_hh[N_NODES * HIDDEN];      // fp16 h = x @ W1 (UNscaled)
__device__ __half   g_h116[N_NODES * HIDDEN];    // fp16 relu(conv1)
__device__ __half   g_lp16[N_NODES * N_CLASSES]; // fp16 lp_pre = dinv * (h1 @ W2)
__device__ unsigned g_W1hi[(N_FEAT / 2) * HIDDEN];   // pre-split W1, bf16x2 [k2][n]
__device__ unsigned g_W1lo[(N_FEAT / 2) * HIDDEN];
__device__ int      g_is64;                      // edge_index dtype flag

// ---------------- bf16 split helper -----------------------------------------
__device__ __forceinline__ void bf16_split2(float x, float y,
                                            unsigned& hi, unsigned& lo) {
    __nv_bfloat16 hx = __float2bfloat16(x);
    __nv_bfloat16 hy = __float2bfloat16(y);
    float lxf = x - __bfloat162float(hx);
    float lyf = y - __bfloat162float(hy);
    __nv_bfloat16 lx = __float2bfloat16(lxf);
    __nv_bfloat16 ly = __float2bfloat16(lyf);
    hi = ((unsigned)__bfloat16_as_ushort(hy) << 16) | (unsigned)__bfloat16_as_ushort(hx);
    lo = ((unsigned)__bfloat16_as_ushort(ly) << 16) | (unsigned)__bfloat16_as_ushort(lx);
}

// ---------------- edge index access (int32 / int64 hedge) ------------------
__device__ __forceinline__ int edge_at(const void* ei, int idx, int is64) {
    if (is64) return (int)((const long long*)ei)[idx];
    return ((const int*)ei)[idx];
}

// zero histogram + detect edge dtype + pre-split W1 to bf16 hi/lo
__global__ void k_zero_cnt(const int* __restrict__ e32,
                           const float* __restrict__ W1) {
    int i = blockIdx.x * blockDim.x + threadIdx.x;
    if (i < N_NODES) g_cnt[i] = 0;
    if (i < (N_FEAT / 2) * HIDDEN) {
        int k2 = i >> 7, n = i & 127;
        float x0 = W1[(size_t)(k2 * 2 + 0) * HIDDEN + n];
        float x1 = W1[(size_t)(k2 * 2 + 1) * HIDDEN + n];
        unsigned h, l;
        bf16_split2(x0, x1, h, l);
        g_W1hi[i] = h;
        g_W1lo[i] = l;
    }
    if (i == 0) {
        bool is64 = true;
        for (int k = 1; k < 64; k += 2) {
            if (e32[k] != 0) { is64 = false; break; }
        }
        g_is64 = is64 ? 1 : 0;
    }
}

__global__ void k_hist(const void* __restrict__ ei, int E) {
    int i = blockIdx.x * blockDim.x + threadIdx.x;
    if (i >= E) return;
    int d = edge_at(ei, E + i, g_is64);
    atomicAdd(&g_cnt[d], 1);
}

// ---------------- hierarchical scan (3 phases, coalesced) -------------------
__global__ __launch_bounds__(256) void k_scan1() {
    __shared__ int sh[256];
    int tid = threadIdx.x;
    int i = blockIdx.x * 256 + tid;
    int c = (i < N_NODES) ? g_cnt[i] : 0;
    sh[tid] = c;
    __syncthreads();
    for (int off = 1; off < 256; off <<= 1) {
        int v = (tid >= off) ? sh[tid - off] : 0;
        __syncthreads();
        sh[tid] += v;
        __syncthreads();
    }
    int incl = sh[tid];
    if (i < N_NODES) g_off[i] = incl - c;
    if (tid == 255) g_blocksum[blockIdx.x] = incl;
}

__global__ __launch_bounds__(256) void k_scan2() {
    __shared__ int sh[256];
    int tid = threadIdx.x;
    int c = (tid < SCAN_BLOCKS) ? g_blocksum[tid] : 0;
    sh[tid] = c;
    __syncthreads();
    for (int off = 1; off < 256; off <<= 1) {
        int v = (tid >= off) ? sh[tid - off] : 0;
        __syncthreads();
        sh[tid] += v;
        __syncthreads();
    }
    if (tid < SCAN_BLOCKS) g_blockoff[tid] = sh[tid] - c;
    if (tid == 255) g_off[N_NODES] = sh[255];
}

__global__ __launch_bounds__(256) void k_scan3() {
    int i = blockIdx.x * 256 + threadIdx.x;
    if (i >= N_NODES) return;
    int off = g_off[i] + g_blockoff[blockIdx.x];
    g_off[i] = off;
    g_pos[i] = off;
    g_dinv[i] = rsqrtf((float)(g_cnt[i] + 1));   // + self loop
}

__global__ void k_scatter(const void* __restrict__ ei, int E) {
    int i = blockIdx.x * blockDim.x + threadIdx.x;
    if (i >= E) return;
    int is64 = g_is64;
    int s = edge_at(ei, i, is64);
    int d = edge_at(ei, E + i, is64);
    int p = atomicAdd(&g_pos[d], 1);
    g_csr_src[p] = s;
}

// ---------------- GEMM1 (tensor cores, bf16x3): g_hh = fp16(x @ W1) ---------
// Fragment-packed smem: A frags stored as contiguous uint4 per (block,gid,tg)
// with XOR swizzle; B frags as uint2 with padded stride. LDS count cut ~3x.
#define MMA_BF16(c, a, b)                                                     \
    asm volatile(                                                             \
        "mma.sync.aligned.m16n8k16.row.col.f32.bf16.bf16.f32 "                \
        "{%0,%1,%2,%3},{%4,%5,%6,%7},{%8,%9},{%0,%1,%2,%3};"                  \
        : "+f"((c)[0]), "+f"((c)[1]), "+f"((c)[2]), "+f"((c)[3])              \
        : "r"((a)[0]), "r"((a)[1]), "r"((a)[2]), "r"((a)[3]),                 \
          "r"((b)[0]), "r"((b)[1]))

__global__ __launch_bounds__(256) void k_sgemm1(const float* __restrict__ A) {
    const int K = N_FEAT, N = HIDDEN, M = N_NODES;
    const int NT = K / 16;   // 32 K-tiles

    // A: 8 m16-blocks x 32 uint4 = 256 uint4 = 1024 words per buffer
    __shared__ __align__(16) unsigned As_hi[2][1024];
    __shared__ __align__(16) unsigned As_lo[2][1024];
    // B: 16 colblocks x 33 uint2 (padded) = 528 uint2 = 1056 words per buffer
    __shared__ __align__(16) unsigned Bs_hi[2][1056];
    __shared__ __align__(16) unsigned Bs_lo[2][1056];

    int tid  = threadIdx.x;
    int lane = tid & 31;
    int wid  = tid >> 5;
    int gid  = lane >> 2;     // 0..7
    int tg   = lane & 3;      // 0..3
    int wm   = (wid >> 2) * 64;
    int wn   = (wid & 3) * 32;
    int blockM = blockIdx.x * 128;

    // ---- A staging mapping ----
    int a_row = tid >> 1;         // 0..127
    int a_q   = tid & 1;          // k2 group 0..3 / 4..7
    int a_rowg = blockM + a_row;
    if (a_rowg > M - 1) a_rowg = M - 1;
    const float* Arow = A + (size_t)a_rowg * K + a_q * 8;

    // fragment-packed write coords for A
    int a_blk  = a_row >> 4;          // m16 block 0..7
    int a_g    = a_row & 7;
    int a_half = (a_row >> 3) & 1;
    int a_word = a_q * 2 + a_half;    // word within uint4

    // ---- B staging mapping ----
    int b_k2 = tid >> 5;          // 0..7 (warp id)
    int b_n0 = (tid & 31) * 4;    // 0..124
    int b_tg = b_k2 & 3;
    int b_up = b_k2 >> 2;

    float c[4][4][4];
#pragma unroll
    for (int mi = 0; mi < 4; mi++)
#pragma unroll
        for (int ni = 0; ni < 4; ni++)
#pragma unroll
            for (int r = 0; r < 4; r++) c[mi][ni][r] = 0.0f;

    float4 fa0, fa1;
    uint4  pbh, pbl;
    fa0 = *(const float4*)(Arow + 0);
    fa1 = *(const float4*)(Arow + 4);
    pbh = *(const uint4*)&g_W1hi[(size_t)b_k2 * HIDDEN + b_n0];
    pbl = *(const uint4*)&g_W1lo[(size_t)b_k2 * HIDDEN + b_n0];

    for (int t = 0; t < NT; t++) {
        int buf = t & 1;

        // ---- convert + store A tile (fragment-packed, XOR swizzle) ----
        {
            unsigned h, l;
            int base4 = a_blk * 32 + a_g * 4;
            int sw = a_g & 3;
            bf16_split2(fa0.x, fa0.y, h, l);
            { int i4 = base4 + (0 ^ sw); As_hi[buf][i4 * 4 + a_word] = h; As_lo[buf][i4 * 4 + a_word] = l; }
            bf16_split2(fa0.z, fa0.w, h, l);
            { int i4 = base4 + (1 ^ sw); As_hi[buf][i4 * 4 + a_word] = h; As_lo[buf][i4 * 4 + a_word] = l; }
            bf16_split2(fa1.x, fa1.y, h, l);
            { int i4 = base4 + (2 ^ sw); As_hi[buf][i4 * 4 + a_word] = h; As_lo[buf][i4 * 4 + a_word] = l; }
            bf16_split2(fa1.z, fa1.w, h, l);
            { int i4 = base4 + (3 ^ sw); As_hi[buf][i4 * 4 + a_word] = h; As_lo[buf][i4 * 4 + a_word] = l; }
        }
        // ---- store pre-split B tile (fragment-packed uint2, padded stride) --
        {
            unsigned hh[4] = {pbh.x, pbh.y, pbh.z, pbh.w};
            unsigned ll[4] = {pbl.x, pbl.y, pbl.z, pbl.w};
#pragma unroll
            for (int j = 0; j < 4; j++) {
                int col = b_n0 + j;
                int i2 = (col >> 3) * 33 + (col & 7) * 4 + b_tg;
                Bs_hi[buf][i2 * 2 + b_up] = hh[j];
                Bs_lo[buf][i2 * 2 + b_up] = ll[j];
            }
        }
        __syncthreads();

        // ---- prefetch next raw tile ----
        if (t + 1 < NT) {
            int kt = (t + 1) * 16;
            fa0 = *(const float4*)(Arow + kt + 0);
            fa1 = *(const float4*)(Arow + kt + 4);
            size_t bidx = (size_t)((t + 1) * 8 + b_k2) * HIDDEN + b_n0;
            pbh = *(const uint4*)&g_W1hi[bidx];
            pbl = *(const uint4*)&g_W1lo[bidx];
        }

        // ---- compute (vectorized fragment loads) ----
        const uint2* Bh2 = (const uint2*)&Bs_hi[buf][0];
        const uint2* Bl2 = (const uint2*)&Bs_lo[buf][0];
        unsigned bh[4][2], bl[4][2];
#pragma unroll
        for (int ni = 0; ni < 4; ni++) {
            int cb = (wn >> 3) + ni;
            uint2 vh = Bh2[cb * 33 + lane];
            uint2 vl = Bl2[cb * 33 + lane];
            bh[ni][0] = vh.x; bh[ni][1] = vh.y;
            bl[ni][0] = vl.x; bl[ni][1] = vl.y;
        }
        const uint4* Ah4 = (const uint4*)&As_hi[buf][0];
        const uint4* Al4 = (const uint4*)&As_lo[buf][0];
        int aswz = gid * 4 + (tg ^ (gid & 3));
#pragma unroll
        for (int mi = 0; mi < 4; mi++) {
            int blk = (wm >> 4) + mi;
            uint4 va = Ah4[blk * 32 + aswz];
            uint4 vb = Al4[blk * 32 + aswz];
            unsigned ah[4] = {va.x, va.y, va.z, va.w};
            unsigned al[4] = {vb.x, vb.y, vb.z, vb.w};
#pragma unroll
            for (int ni = 0; ni < 4; ni++) MMA_BF16(c[mi][ni], ah, bh[ni]);
#pragma unroll
            for (int ni = 0; ni < 4; ni++) MMA_BF16(c[mi][ni], ah, bl[ni]);
#pragma unroll
            for (int ni = 0; ni < 4; ni++) MMA_BF16(c[mi][ni], al, bh[ni]);
        }
    }

    // ---- epilogue: g_hh = fp16(C)  (unscaled; dinv applied in agg1) ----
#pragma unroll
    for (int mi = 0; mi < 4; mi++) {
        int r0 = blockM + wm + mi * 16 + gid;
        int r1 = r0 + 8;
#pragma unroll
        for (int ni = 0; ni < 4; ni++) {
            int col = wn + ni * 8 + tg * 2;
            if (r0 < M)
                *(__half2*)&g_hh[(size_t)r0 * N + col] =
                    __floats2half2_rn(c[mi][ni][0], c[mi][ni][1]);
            if (r1 < M)
                *(__half2*)&g_hh[(size_t)r1 * N + col] =
                    __floats2half2_rn(c[mi][ni][2], c[mi][ni][3]);
        }
    }
}

// ---------------- layer-1 aggregation (fp16 gather, simple 8-batch) ---------
__global__ __launch_bounds__(256) void k_agg1(const float* __restrict__ b1) {
    int node = (blockIdx.x * blockDim.x + threadIdx.x) >> 5;
    if (node >= N_NODES) return;
    int lane = threadIdx.x & 31;

    const uint2* hp = (const uint2*)g_hh;
    float di = g_dinv[node];
    int beg = g_off[node];
    int end = g_off[node + 1];

    float ax, ay, az, aw;
    {
        uint2 raw = __ldg(&hp[(size_t)node * 32 + lane]);   // self loop
        float2 f0 = __half22float2(*(__half2*)&raw.x);
        float2 f1 = __half22float2(*(__half2*)&raw.y);
        ax = di * f0.x; ay = di * f0.y; az = di * f1.x; aw = di * f1.y;
    }

    int e = beg;
    for (; e + 8 <= end; e += 8) {
        int   si[8];
        float wt[8];
        uint2 r[8];
#pragma unroll
        for (int j = 0; j < 8; j++) si[j] = __ldg(&g_csr_src[e + j]);
#pragma unroll
        for (int j = 0; j < 8; j++) wt[j] = __ldg(&g_dinv[si[j]]);
#pragma unroll
        for (int j = 0; j < 8; j++) r[j] = __ldg(&hp[(size_t)si[j] * 32 + lane]);
#pragma unroll
        for (int j = 0; j < 8; j++) {
            float2 a = __half22float2(*(__half2*)&r[j].x);
            float2 b = __half22float2(*(__half2*)&r[j].y);
            ax += wt[j] * a.x; ay += wt[j] * a.y;
            az += wt[j] * b.x; aw += wt[j] * b.y;
        }
    }
    for (; e < end; e++) {
        int s = __ldg(&g_csr_src[e]);
        float wt = __ldg(&g_dinv[s]);
        uint2 r = __ldg(&hp[(size_t)s * 32 + lane]);
        float2 a = __half22float2(*(__half2*)&r.x);
        float2 b = __half22float2(*(__half2*)&r.y);
        ax += wt * a.x; ay += wt * a.y; az += wt * b.x; aw += wt * b.y;
    }

    float4 bb = *(const float4*)&b1[lane * 4];
    float ox = fmaxf(di * ax + bb.x, 0.0f);
    float oy = fmaxf(di * ay + bb.y, 0.0f);
    float oz = fmaxf(di * az + bb.z, 0.0f);
    float ow = fmaxf(di * aw + bb.w, 0.0f);
    uint2 st;
    *(__half2*)&st.x = __floats2half2_rn(ox, oy);
    *(__half2*)&st.y = __floats2half2_rn(oz, ow);
    *(uint2*)&g_h116[(size_t)node * HIDDEN + lane * 4] = st;
}

// ---------------- GEMM2: g_lp16 = fp16(dinv * (h1 @ W2)), fp16 h1 input -----
__global__ __launch_bounds__(256) void k_gemm2(const float* __restrict__ W2) {
    __shared__ float sW[HIDDEN * N_CLASSES];
    __shared__ float sH[32 * HIDDEN];
    int tid = threadIdx.x;
    int row0 = blockIdx.x * 32;

    for (int i = tid; i < HIDDEN * N_CLASSES; i += 256) sW[i] = W2[i];
    for (int i = tid; i < 32 * HIDDEN / 4; i += 256) {
        int r = i >> 5;
        int c4 = i & 31;
        int grow = row0 + r;
        float4 v = make_float4(0.f, 0.f, 0.f, 0.f);
        if (grow < N_NODES) {
            uint2 raw = *(const uint2*)&g_h116[(size_t)grow * HIDDEN + c4 * 4];
            float2 f0 = __half22float2(*(__half2*)&raw.x);
            float2 f1 = __half22float2(*(__half2*)&raw.y);
            v = make_float4(f0.x, f0.y, f1.x, f1.y);
        }
        *(float4*)&sH[r * HIDDEN + c4 * 4] = v;
    }
    __syncthreads();

#pragma unroll
    for (int p = 0; p < 5; p++) {
        int o = tid + p * 256;
        int r = o / N_CLASSES;
        int c = o - r * N_CLASSES;
        float acc = 0.0f;
#pragma unroll 8
        for (int k = 0; k < HIDDEN; k++) acc += sH[r * HIDDEN + k] * sW[k * N_CLASSES + c];
        int grow = row0 + r;
        if (grow < N_NODES)
            g_lp16[(size_t)grow * N_CLASSES + c] = __float2half(g_dinv[grow] * acc);
    }
}

// ---------------- layer-2 aggregation + bias + log_softmax (fp16 gather) ----
__global__ __launch_bounds__(256) void k_agg2(const float* __restrict__ b2,
                                              float* __restrict__ out,
                                              int write_logits) {
    int warp = (blockIdx.x * blockDim.x + threadIdx.x) >> 5;
    if (warp >= N_NODES) return;
    int lane = threadIdx.x & 31;
    bool act = (lane < 20);

    const __half2* lp = (const __half2*)g_lp16;   // 20 half2 per row
    float di = g_dinv[warp];
    int beg = g_off[warp];
    int end = g_off[warp + 1];

    float a0 = 0.0f, a1 = 0.0f;
    if (act) {
        float2 f = __half22float2(__ldg(&lp[(size_t)warp * 20 + lane]));   // self loop
        a0 = f.x; a1 = f.y;
    }

    int e = beg;
    for (; e + 8 <= end; e += 8) {
        int si[8];
#pragma unroll
        for (int j = 0; j < 8; j++) si[j] = __ldg(&g_csr_src[e + j]);
        if (act) {
            __half2 r[8];
#pragma unroll
            for (int j = 0; j < 8; j++) r[j] = __ldg(&lp[(size_t)si[j] * 20 + lane]);
#pragma unroll
            for (int j = 0; j < 8; j++) {
                float2 f = __half22float2(r[j]);
                a0 += f.x; a1 += f.y;
            }
        }
    }
    for (; e < end; e++) {
        int s = __ldg(&g_csr_src[e]);
        if (act) {
            float2 f = __half22float2(__ldg(&lp[(size_t)s * 20 + lane]));
            a0 += f.x; a1 += f.y;
        }
    }

    float v0 = act ? di * a0 + b2[lane * 2 + 0] : -INFINITY;
    float v1 = act ? di * a1 + b2[lane * 2 + 1] : -INFINITY;

    float m = fmaxf(v0, v1);
#pragma unroll
    for (int off = 16; off > 0; off >>= 1)
        m = fmaxf(m, __shfl_xor_sync(0xFFFFFFFFu, m, off));

    float sum = act ? (__expf(v0 - m) + __expf(v1 - m)) : 0.0f;
#pragma unroll
    for (int off = 16; off > 0; off >>= 1)
        sum += __shfl_xor_sync(0xFFFFFFFFu, sum, off);

    float lse = m + logf(sum);

    if (act) {
        *(float2*)&out[(size_t)warp * N_CLASSES + lane * 2] =
            make_float2(v0 - lse, v1 - lse);
        if (write_logits) {
            *(float2*)&out[(size_t)N_NODES * N_CLASSES + (size_t)warp * N_CLASSES + lane * 2] =
                make_float2(v0, v1);
        }
    }
}

// ---------------- launch -----------------------------------------------------
extern "C" void kernel_launch(void* const* d_in, const int* in_sizes, int n_in,
                              void* d_out, int out_size) {
    const float* x  = (const float*)d_in[0];
    const void*  ei = d_in[1];
    const float* W1 = (const float*)d_in[2];
    const float* b1 = (const float*)d_in[3];
    const float* W2 = (const float*)d_in[4];
    const float* b2 = (const float*)d_in[5];
    float* out = (float*)d_out;

    int E = in_sizes[1] / 2;
    if (E > E_MAX) E = E_MAX;
    int write_logits = (out_size >= 2 * N_NODES * N_CLASSES) ? 1 : 0;

    // side stream + fork/join events, created once on the first (un-captured) call.
    static cudaStream_t s2 = nullptr;
    static cudaEvent_t  evFork = nullptr, evJoin = nullptr;
    if (s2 == nullptr) {
        cudaStreamCreateWithFlags(&s2, cudaStreamNonBlocking);
        cudaEventCreateWithFlags(&evFork, cudaEventDisableTiming);
        cudaEventCreateWithFlags(&evJoin, cudaEventDisableTiming);
    }

    // stream 0: W1 split + zero cnt
    k_zero_cnt<<<(N_NODES + 255) / 256, 256>>>((const int*)ei, W1);

    // fork: GEMM1 on s2; CSR build on stream 0 (hidden behind GEMM1)
    cudaEventRecord(evFork, 0);
    cudaStreamWaitEvent(s2, evFork, 0);
    k_sgemm1<<<(N_NODES + 127) / 128, 256, 0, s2>>>(x);
    cudaEventRecord(evJoin, s2);

    k_hist<<<(E + 255) / 256, 256>>>(ei, E);
    k_scan1<<<SCAN_BLOCKS, 256>>>();
    k_scan2<<<1, 256>>>();
    k_scan3<<<SCAN_BLOCKS, 256>>>();
    k_scatter<<<(E + 255) / 256, 256>>>(ei, E);

    // join: agg1 needs GEMM1 output + CSR + dinv; serial tail
    cudaStreamWaitEvent(0, evJoin, 0);
    k_agg1<<<(N_NODES * 32 + 255) / 256, 256>>>(b1);
    k_gemm2<<<(N_NODES + 31) / 32, 256>>>(W2);
    k_agg2<<<(N_NODES * 32 + 255) / 256, 256>>>(b2, out, write_logits);
}